// round 2
// baseline (speedup 1.0000x reference)
#include <cuda_runtime.h>
#include <math.h>

#define T_TOK 8192
#define D_DIM 1024
#define F_DIM 2048
#define E_EXP 8
#define KSEL  2
#define CAP   8192   // per-expert worst-case capacity

#define BM 64
#define BN 64
#define BK 16

// Scratch (allocation-free rule: __device__ globals)
__device__ float  g_H[(size_t)E_EXP * CAP * F_DIM];   // SwiGLU activations per assignment slot
__device__ int    g_cnt[E_EXP];
__device__ int    g_tok[E_EXP * CAP];
__device__ float  g_wt [E_EXP * CAP];
__device__ double g_psum[E_EXP];
__device__ double g_zsum;

__global__ void init_kernel() {
    int i = threadIdx.x;
    if (i < E_EXP) { g_cnt[i] = 0; g_psum[i] = 0.0; }
    if (i == 0) g_zsum = 0.0;
}

// One warp per token (grid-stride). Computes logits = x@Wr, softmax, top-2,
// renormalized combine weights, appends (token, weight) to its experts'
// segments, and accumulates aux-loss statistics (block-reduced, then global
// double atomics to keep contention trivial).
__global__ void router_kernel(const float* __restrict__ x,
                              const float* __restrict__ Wr) {
    __shared__ double s_ps[E_EXP];
    __shared__ double s_zs;
    int tid = threadIdx.x;
    if (tid < E_EXP) s_ps[tid] = 0.0;
    if (tid == 0) s_zs = 0.0;
    __syncthreads();

    int lane = tid & 31;
    int warp = tid >> 5;
    int nwarps_total = (gridDim.x * blockDim.x) >> 5;
    int gwarp = blockIdx.x * (blockDim.x >> 5) + warp;

    double lps[E_EXP];
#pragma unroll
    for (int e = 0; e < E_EXP; e++) lps[e] = 0.0;
    double lzs = 0.0;

    for (int t = gwarp; t < T_TOK; t += nwarps_total) {
        const float* xr = x + (size_t)t * D_DIM;
        float acc[E_EXP];
#pragma unroll
        for (int e = 0; e < E_EXP; e++) acc[e] = 0.f;
        for (int i = lane; i < D_DIM; i += 32) {
            float xv = xr[i];
#pragma unroll
            for (int e = 0; e < E_EXP; e++)
                acc[e] = fmaf(xv, Wr[i * E_EXP + e], acc[e]);
        }
#pragma unroll
        for (int e = 0; e < E_EXP; e++) {
#pragma unroll
            for (int o = 16; o > 0; o >>= 1)
                acc[e] += __shfl_xor_sync(0xffffffffu, acc[e], o);
        }
        if (lane == 0) {
            float m = acc[0];
#pragma unroll
            for (int e = 1; e < E_EXP; e++) m = fmaxf(m, acc[e]);
            float s = 0.f, p[E_EXP];
#pragma unroll
            for (int e = 0; e < E_EXP; e++) { p[e] = expf(acc[e] - m); s += p[e]; }
            float inv = 1.f / s;
#pragma unroll
            for (int e = 0; e < E_EXP; e++) { p[e] *= inv; lps[e] += (double)p[e]; }
            float lse = m + logf(s);
            lzs += (double)lse * (double)lse;

            // top-2 (by logits; softmax is monotone). First index wins ties.
            int i0 = 0; float v0 = acc[0];
#pragma unroll
            for (int e = 1; e < E_EXP; e++) if (acc[e] > v0) { v0 = acc[e]; i0 = e; }
            int i1 = -1; float v1 = -INFINITY;
#pragma unroll
            for (int e = 0; e < E_EXP; e++)
                if (e != i0 && acc[e] > v1) { v1 = acc[e]; i1 = e; }

            float pv0 = p[i0], pv1 = p[i1];
            float rinv = 1.f / (pv0 + pv1);
            float w0 = pv0 * rinv, w1 = pv1 * rinv;

            int pos0 = atomicAdd(&g_cnt[i0], 1);
            g_tok[i0 * CAP + pos0] = t; g_wt[i0 * CAP + pos0] = w0;
            int pos1 = atomicAdd(&g_cnt[i1], 1);
            g_tok[i1 * CAP + pos1] = t; g_wt[i1 * CAP + pos1] = w1;
        }
    }
    if (lane == 0) {
#pragma unroll
        for (int e = 0; e < E_EXP; e++) atomicAdd(&s_ps[e], lps[e]);
        atomicAdd(&s_zs, lzs);
    }
    __syncthreads();
    if (tid < E_EXP) atomicAdd(&g_psum[tid], s_ps[tid]);
    if (tid == 0) atomicAdd(&g_zsum, s_zs);
}

// GEMM1: H[slot] = silu(X_e @ Wg_e) * (X_e @ Wu_e)
// 64x64 tile, BK=16, 256 threads, 4x4 register tile per matrix (G and U share A).
__global__ void gemm1_kernel(const float* __restrict__ x,
                             const float* __restrict__ Wg,
                             const float* __restrict__ Wu) {
    int e = blockIdx.z;
    int n = g_cnt[e];
    int row0 = blockIdx.y * BM;
    if (row0 >= n) return;
    int col0 = blockIdx.x * BN;

    __shared__ float Xs[BM][BK + 1];
    __shared__ float Gs[BK][BN];
    __shared__ float Us[BK][BN];
    __shared__ int   toks[BM];

    int tid = threadIdx.x;
    if (tid < BM) {
        int r = row0 + tid;
        toks[tid] = (r < n) ? g_tok[e * CAP + r] : -1;
    }
    __syncthreads();

    int tx = tid & 15, ty = tid >> 4;
    float accG[4][4] = {}, accU[4][4] = {};
    const float* Wge = Wg + (size_t)e * D_DIM * F_DIM;
    const float* Wue = Wu + (size_t)e * D_DIM * F_DIM;

    int xc = (tid & 3) * 4;   // float4 column within BK
    int xr = tid >> 2;        // 0..63
    int wc = (tid & 15) * 4;  // float4 column within BN
    int wr = tid >> 4;        // 0..15

    int mytok = toks[xr];

    for (int k0 = 0; k0 < D_DIM; k0 += BK) {
        float4 xv = make_float4(0.f, 0.f, 0.f, 0.f);
        if (mytok >= 0)
            xv = *(const float4*)(x + (size_t)mytok * D_DIM + k0 + xc);
        Xs[xr][xc + 0] = xv.x; Xs[xr][xc + 1] = xv.y;
        Xs[xr][xc + 2] = xv.z; Xs[xr][xc + 3] = xv.w;
        *(float4*)&Gs[wr][wc] = *(const float4*)(Wge + (size_t)(k0 + wr) * F_DIM + col0 + wc);
        *(float4*)&Us[wr][wc] = *(const float4*)(Wue + (size_t)(k0 + wr) * F_DIM + col0 + wc);
        __syncthreads();
#pragma unroll
        for (int kk = 0; kk < BK; kk++) {
            float a[4];
#pragma unroll
            for (int i = 0; i < 4; i++) a[i] = Xs[ty * 4 + i][kk];
            float4 bg = *(float4*)&Gs[kk][tx * 4];
            float4 bu = *(float4*)&Us[kk][tx * 4];
            float bgv[4] = {bg.x, bg.y, bg.z, bg.w};
            float buv[4] = {bu.x, bu.y, bu.z, bu.w};
#pragma unroll
            for (int i = 0; i < 4; i++)
#pragma unroll
                for (int j = 0; j < 4; j++) {
                    accG[i][j] = fmaf(a[i], bgv[j], accG[i][j]);
                    accU[i][j] = fmaf(a[i], buv[j], accU[i][j]);
                }
        }
        __syncthreads();
    }

#pragma unroll
    for (int i = 0; i < 4; i++) {
        int row = row0 + ty * 4 + i;
        if (row < n) {
            float4 hv;
            float* hp = &hv.x;
#pragma unroll
            for (int j = 0; j < 4; j++) {
                float g = accG[i][j];
                float sg = g / (1.f + expf(-g));
                hp[j] = sg * accU[i][j];
            }
            *(float4*)&g_H[((size_t)e * CAP + row) * F_DIM + col0 + tx * 4] = hv;
        }
    }
}

// GEMM2: out[tok] += w_slot * (H[slot] @ Wd_e)
__global__ void gemm2_kernel(const float* __restrict__ Wd,
                             float* __restrict__ out) {
    int e = blockIdx.z;
    int n = g_cnt[e];
    int row0 = blockIdx.y * BM;
    if (row0 >= n) return;
    int col0 = blockIdx.x * BN;

    __shared__ float Hs[BM][BK + 1];
    __shared__ float Ds[BK][BN];
    __shared__ int   toks[BM];
    __shared__ float wts[BM];

    int tid = threadIdx.x;
    if (tid < BM) {
        int r = row0 + tid;
        toks[tid] = (r < n) ? g_tok[e * CAP + r] : -1;
        wts[tid]  = (r < n) ? g_wt[e * CAP + r] : 0.f;
    }
    __syncthreads();

    int tx = tid & 15, ty = tid >> 4;
    float acc[4][4] = {};
    const float* Wde = Wd + (size_t)e * F_DIM * D_DIM;
    const float* Hbase = &g_H[((size_t)e * CAP + row0) * F_DIM];

    int xc = (tid & 3) * 4;
    int xr = tid >> 2;
    int wc = (tid & 15) * 4;
    int wr = tid >> 4;
    bool rowok = (row0 + xr) < n;

    for (int k0 = 0; k0 < F_DIM; k0 += BK) {
        float4 hv = make_float4(0.f, 0.f, 0.f, 0.f);
        if (rowok)
            hv = *(const float4*)(Hbase + (size_t)xr * F_DIM + k0 + xc);
        Hs[xr][xc + 0] = hv.x; Hs[xr][xc + 1] = hv.y;
        Hs[xr][xc + 2] = hv.z; Hs[xr][xc + 3] = hv.w;
        *(float4*)&Ds[wr][wc] = *(const float4*)(Wde + (size_t)(k0 + wr) * D_DIM + col0 + wc);
        __syncthreads();
#pragma unroll
        for (int kk = 0; kk < BK; kk++) {
            float a[4];
#pragma unroll
            for (int i = 0; i < 4; i++) a[i] = Hs[ty * 4 + i][kk];
            float4 b = *(float4*)&Ds[kk][tx * 4];
            float bv[4] = {b.x, b.y, b.z, b.w};
#pragma unroll
            for (int i = 0; i < 4; i++)
#pragma unroll
                for (int j = 0; j < 4; j++)
                    acc[i][j] = fmaf(a[i], bv[j], acc[i][j]);
        }
        __syncthreads();
    }

#pragma unroll
    for (int i = 0; i < 4; i++) {
        int r = ty * 4 + i;
        if (row0 + r < n) {
            int tok = toks[r];
            float w = wts[r];
            float* orow = out + (size_t)tok * D_DIM + col0 + tx * 4;
#pragma unroll
            for (int j = 0; j < 4; j++)
                atomicAdd(&orow[j], w * acc[i][j]);
        }
    }
}

__global__ void finalize_kernel(float* __restrict__ out, long long out_elems) {
    if (threadIdx.x == 0 && blockIdx.x == 0) {
        double lb = 0.0;
        for (int e = 0; e < E_EXP; e++) {
            double f = (double)g_cnt[e] / (double)(T_TOK * KSEL);
            double P = g_psum[e] / (double)T_TOK;
            lb += f * P;
        }
        lb *= (double)E_EXP;
        double z = g_zsum / (double)T_TOK;
        double aux = 0.01 * lb + 0.001 * z;
        long long idx = (long long)T_TOK * D_DIM;
        if (out_elems > idx) out[idx] = (float)aux;
    }
}

extern "C" void kernel_launch(void* const* d_in, const int* in_sizes, int n_in,
                              void* d_out, int out_size) {
    const float* x  = (const float*)d_in[0];
    const float* Wr = (const float*)d_in[1];
    const float* Wg = (const float*)d_in[2];
    const float* Wu = (const float*)d_in[3];
    const float* Wd = (const float*)d_in[4];
    float* out = (float*)d_out;

    cudaMemsetAsync(out, 0, (size_t)out_size * sizeof(float), 0);
    init_kernel<<<1, 32>>>();
    router_kernel<<<128, 256>>>(x, Wr);
    dim3 g1(F_DIM / BN, CAP / BM, E_EXP);
    gemm1_kernel<<<g1, 256>>>(x, Wg, Wu);
    dim3 g2(D_DIM / BN, CAP / BM, E_EXP);
    gemm2_kernel<<<g2, 256>>>(Wd, out);
    finalize_kernel<<<1, 32>>>(out, (long long)out_size);
}

// round 5
// speedup vs baseline: 4.6765x; 4.6765x over previous
#include <cuda_runtime.h>
#include <cstdint>
#include <math.h>

#define T_TOK 8192
#define D_DIM 1024
#define F_DIM 2048
#define E_EXP 8
#define KSEL  2
#define CAP   8192

// ---------------- device scratch (no allocations allowed) ----------------
__device__ float    g_H  [(size_t)E_EXP * CAP * F_DIM];      // SwiGLU acts (tf32-rounded)
__device__ uint32_t g_xt [(size_t)T_TOK * D_DIM];            // tf32(x)
__device__ uint32_t g_wgt[(size_t)E_EXP * D_DIM * F_DIM];    // tf32(Wg)
__device__ uint32_t g_wut[(size_t)E_EXP * D_DIM * F_DIM];    // tf32(Wu)
__device__ uint32_t g_wdt[(size_t)E_EXP * F_DIM * D_DIM];    // tf32(Wd)
__device__ int      g_cnt[E_EXP];
__device__ int      g_tok[E_EXP * CAP];
__device__ float    g_wt [E_EXP * CAP];
__device__ double   g_psum[E_EXP];
__device__ double   g_zsum;

// ---------------- helpers ----------------
__device__ __forceinline__ uint32_t f2tf(float f) {
    uint32_t r;
    asm("cvt.rna.tf32.f32 %0, %1;" : "=r"(r) : "f"(f));
    return r;
}
__device__ __forceinline__ uint32_t s2u(const void* p) {
    uint32_t a;
    asm("{ .reg .u64 t; cvta.to.shared.u64 t, %1; cvt.u32.u64 %0, t; }" : "=r"(a) : "l"(p));
    return a;
}
#define CPA16(dst, src) \
    asm volatile("cp.async.cg.shared.global [%0], [%1], 16;" :: "r"((uint32_t)(dst)), "l"(src) : "memory")
#define CPCOMMIT() asm volatile("cp.async.commit_group;" ::: "memory")
#define CPWAIT1()  asm volatile("cp.async.wait_group 1;" ::: "memory")

__device__ __forceinline__ void mma8(float* d, const uint32_t* a, const uint32_t* b) {
    asm volatile("mma.sync.aligned.m16n8k8.row.col.f32.tf32.tf32.f32 "
                 "{%0,%1,%2,%3}, {%4,%5,%6,%7}, {%8,%9}, {%0,%1,%2,%3};"
                 : "+f"(d[0]), "+f"(d[1]), "+f"(d[2]), "+f"(d[3])
                 : "r"(a[0]), "r"(a[1]), "r"(a[2]), "r"(a[3]), "r"(b[0]), "r"(b[1]));
}

// SMEM strides (words) — padded for conflict-free fragment loads
#define SA 36    // A tile: 128 rows x 32 k (pad +4)
#define SB 132   // B tile: 32 k x 128 n (pad +4)
#define ABYTES (128 * SA * 4)   // 18432
#define BBYTES (32 * SB * 4)    // 16896
#define STAGE1 (ABYTES + 2 * BBYTES)  // 52224
#define STAGE2 (ABYTES + BBYTES)      // 35328
#define BUF0   1024
#define SMEM1  (BUF0 + 2 * STAGE1)    // 105472
#define SMEM2  (BUF0 + 2 * STAGE2)    // 71680

// ---------------- small kernels ----------------
__global__ void init_kernel() {
    int i = threadIdx.x;
    if (i < E_EXP) { g_cnt[i] = 0; g_psum[i] = 0.0; }
    if (i == 0) g_zsum = 0.0;
}

__global__ void cvt_all(const float* __restrict__ x, const float* __restrict__ wg,
                        const float* __restrict__ wu, const float* __restrict__ wd) {
    int stride = gridDim.x * blockDim.x;
    int i0 = blockIdx.x * blockDim.x + threadIdx.x;
    const int nx = T_TOK * D_DIM / 4;
    const int nw = E_EXP * D_DIM * F_DIM / 4;
    for (int i = i0; i < nx; i += stride) {
        float4 v = ((const float4*)x)[i];
        ((uint4*)g_xt)[i] = make_uint4(f2tf(v.x), f2tf(v.y), f2tf(v.z), f2tf(v.w));
    }
    for (int i = i0; i < nw; i += stride) {
        float4 v = ((const float4*)wg)[i];
        ((uint4*)g_wgt)[i] = make_uint4(f2tf(v.x), f2tf(v.y), f2tf(v.z), f2tf(v.w));
    }
    for (int i = i0; i < nw; i += stride) {
        float4 v = ((const float4*)wu)[i];
        ((uint4*)g_wut)[i] = make_uint4(f2tf(v.x), f2tf(v.y), f2tf(v.z), f2tf(v.w));
    }
    for (int i = i0; i < nw; i += stride) {
        float4 v = ((const float4*)wd)[i];
        ((uint4*)g_wdt)[i] = make_uint4(f2tf(v.x), f2tf(v.y), f2tf(v.z), f2tf(v.w));
    }
}

__global__ void router_kernel(const float* __restrict__ x,
                              const float* __restrict__ Wr) {
    __shared__ double s_ps[E_EXP];
    __shared__ double s_zs;
    int tid = threadIdx.x;
    if (tid < E_EXP) s_ps[tid] = 0.0;
    if (tid == 0) s_zs = 0.0;
    __syncthreads();
    int lane = tid & 31, warp = tid >> 5;
    int nw = (gridDim.x * blockDim.x) >> 5;
    int gw = blockIdx.x * (blockDim.x >> 5) + warp;
    double lps[E_EXP];
#pragma unroll
    for (int e = 0; e < E_EXP; e++) lps[e] = 0.0;
    double lzs = 0.0;
    for (int t = gw; t < T_TOK; t += nw) {
        const float* xr = x + (size_t)t * D_DIM;
        float acc[E_EXP];
#pragma unroll
        for (int e = 0; e < E_EXP; e++) acc[e] = 0.f;
        for (int i = lane; i < D_DIM; i += 32) {
            float xv = xr[i];
#pragma unroll
            for (int e = 0; e < E_EXP; e++)
                acc[e] = fmaf(xv, Wr[i * E_EXP + e], acc[e]);
        }
#pragma unroll
        for (int e = 0; e < E_EXP; e++)
#pragma unroll
            for (int o = 16; o > 0; o >>= 1)
                acc[e] += __shfl_xor_sync(0xffffffffu, acc[e], o);
        if (lane == 0) {
            float m = acc[0];
#pragma unroll
            for (int e = 1; e < E_EXP; e++) m = fmaxf(m, acc[e]);
            float s = 0.f, p[E_EXP];
#pragma unroll
            for (int e = 0; e < E_EXP; e++) { p[e] = expf(acc[e] - m); s += p[e]; }
            float inv = 1.f / s;
#pragma unroll
            for (int e = 0; e < E_EXP; e++) { p[e] *= inv; lps[e] += (double)p[e]; }
            float lse = m + logf(s);
            lzs += (double)lse * (double)lse;
            int i0 = 0; float v0 = acc[0];
#pragma unroll
            for (int e = 1; e < E_EXP; e++) if (acc[e] > v0) { v0 = acc[e]; i0 = e; }
            int i1 = -1; float v1 = -INFINITY;
#pragma unroll
            for (int e = 0; e < E_EXP; e++)
                if (e != i0 && acc[e] > v1) { v1 = acc[e]; i1 = e; }
            float rinv = 1.f / (p[i0] + p[i1]);
            int p0 = atomicAdd(&g_cnt[i0], 1);
            g_tok[i0 * CAP + p0] = t; g_wt[i0 * CAP + p0] = p[i0] * rinv;
            int p1 = atomicAdd(&g_cnt[i1], 1);
            g_tok[i1 * CAP + p1] = t; g_wt[i1 * CAP + p1] = p[i1] * rinv;
        }
    }
    if (lane == 0) {
#pragma unroll
        for (int e = 0; e < E_EXP; e++) atomicAdd(&s_ps[e], lps[e]);
        atomicAdd(&s_zs, lzs);
    }
    __syncthreads();
    if (tid < E_EXP) atomicAdd(&g_psum[tid], s_ps[tid]);
    if (tid == 0) atomicAdd(&g_zsum, s_zs);
}

__global__ void finalize_kernel(float* __restrict__ out, long long out_elems) {
    if (threadIdx.x == 0 && blockIdx.x == 0) {
        double lb = 0.0;
        for (int e = 0; e < E_EXP; e++)
            lb += ((double)g_cnt[e] / (double)(T_TOK * KSEL)) * (g_psum[e] / (double)T_TOK);
        lb *= (double)E_EXP;
        double aux = 0.01 * lb + 0.001 * (g_zsum / (double)T_TOK);
        long long idx = (long long)T_TOK * D_DIM;
        if (out_elems > idx) out[idx] = (float)aux;
    }
}

// ---------------- GEMM1: H = silu(X Wg) * (X Wu), tf32 mma.sync ----------------
__global__ __launch_bounds__(256, 1)
void gemm1_mma(const float* dummy) {
    int e = blockIdx.z;
    int n = g_cnt[e];
    int row0 = blockIdx.y * 128;
    if (row0 >= n) return;
    int col0 = blockIdx.x * 128;

    extern __shared__ char smem[];
    int* toks = (int*)smem;
    uint32_t sb = s2u(smem);
    int tid = threadIdx.x, wid = tid >> 5, l = tid & 31;

    if (tid < 128) {
        int r = row0 + tid;
        toks[tid] = (r < n) ? g_tok[e * CAP + r] : g_tok[e * CAP];
    }
    __syncthreads();

    // A copy role: 2 threads per row, 4 chunks each (32 k-words per row)
    int arow = tid >> 1;               // 0..127
    int aseg0 = (tid & 1) * 4;
    int tok = toks[arow];
    const uint32_t* srcA = g_xt + (size_t)tok * D_DIM;
    // B copy role: 8 threads per k-row, 4 column-group chunks each (128 n-words)
    int brow = tid >> 3, bseg = tid & 7;
    const uint32_t* srcG = g_wgt + (size_t)e * D_DIM * F_DIM + (size_t)brow * F_DIM + col0 + bseg * 4;
    const uint32_t* srcU = g_wut + (size_t)e * D_DIM * F_DIM + (size_t)brow * F_DIM + col0 + bseg * 4;
    uint32_t adst[4], bdst[4];
#pragma unroll
    for (int j = 0; j < 4; j++) {
        adst[j] = (uint32_t)((arow * SA + (aseg0 + j) * 4) * 4);
        bdst[j] = (uint32_t)((brow * SB + bseg * 4 + j * 32) * 4);
    }

    const int NT = D_DIM / 32;  // 32

#define G1_ISSUE(c) do { \
    uint32_t base_ = sb + BUF0 + ((c) & 1) * STAGE1; \
    int k0_ = (c) * 32; \
    const uint32_t* sa_ = srcA + k0_ + aseg0 * 4; \
    const uint32_t* sg_ = srcG + (size_t)k0_ * F_DIM; \
    const uint32_t* su_ = srcU + (size_t)k0_ * F_DIM; \
    CPA16(base_ + adst[0], sa_); \
    CPA16(base_ + adst[1], sa_ + 4); \
    CPA16(base_ + adst[2], sa_ + 8); \
    CPA16(base_ + adst[3], sa_ + 12); \
    CPA16(base_ + ABYTES + bdst[0], sg_); \
    CPA16(base_ + ABYTES + bdst[1], sg_ + 32); \
    CPA16(base_ + ABYTES + bdst[2], sg_ + 64); \
    CPA16(base_ + ABYTES + bdst[3], sg_ + 96); \
    CPA16(base_ + ABYTES + BBYTES + bdst[0], su_); \
    CPA16(base_ + ABYTES + BBYTES + bdst[1], su_ + 32); \
    CPA16(base_ + ABYTES + BBYTES + bdst[2], su_ + 64); \
    CPA16(base_ + ABYTES + BBYTES + bdst[3], su_ + 96); \
} while (0)

    float accG[4][4][4] = {}, accU[4][4][4] = {};
    int wm = wid & 1, wn = wid >> 1;
    int qr = l >> 2, qc = l & 3;

    G1_ISSUE(0); CPCOMMIT();
    G1_ISSUE(1); CPCOMMIT();

#pragma unroll 1
    for (int c = 0; c < NT; c++) {
        CPWAIT1();
        __syncthreads();
        const uint32_t* As = (const uint32_t*)(smem + BUF0 + (c & 1) * STAGE1);
        const uint32_t* Gs = As + ABYTES / 4;
        const uint32_t* Us = As + (ABYTES + BBYTES) / 4;
#pragma unroll
        for (int ks = 0; ks < 4; ks++) {
            int kk = ks * 8;
            uint32_t af[4][4];
#pragma unroll
            for (int mt = 0; mt < 4; mt++) {
                int r0 = wm * 64 + mt * 16 + qr;
                af[mt][0] = As[r0 * SA + kk + qc];
                af[mt][1] = As[(r0 + 8) * SA + kk + qc];
                af[mt][2] = As[r0 * SA + kk + qc + 4];
                af[mt][3] = As[(r0 + 8) * SA + kk + qc + 4];
            }
            uint32_t bg[4][2], bu[4][2];
#pragma unroll
            for (int nt = 0; nt < 4; nt++) {
                int cc = wn * 32 + nt * 8 + qr;
                bg[nt][0] = Gs[(kk + qc) * SB + cc];
                bg[nt][1] = Gs[(kk + qc + 4) * SB + cc];
                bu[nt][0] = Us[(kk + qc) * SB + cc];
                bu[nt][1] = Us[(kk + qc + 4) * SB + cc];
            }
#pragma unroll
            for (int mt = 0; mt < 4; mt++)
#pragma unroll
                for (int nt = 0; nt < 4; nt++) {
                    mma8(accG[mt][nt], af[mt], bg[nt]);
                    mma8(accU[mt][nt], af[mt], bu[nt]);
                }
        }
        __syncthreads();
        if (c + 2 < NT) G1_ISSUE(c + 2);
        CPCOMMIT();
    }

    // epilogue: SwiGLU -> g_H (tf32-rounded)
#pragma unroll
    for (int mt = 0; mt < 4; mt++)
#pragma unroll
        for (int half = 0; half < 2; half++) {
            int grow = row0 + wm * 64 + mt * 16 + qr + half * 8;
            if (grow < n) {
                float* hrow = &g_H[((size_t)e * CAP + grow) * F_DIM + col0];
#pragma unroll
                for (int nt = 0; nt < 4; nt++) {
                    float g0 = accG[mt][nt][half * 2], g1 = accG[mt][nt][half * 2 + 1];
                    float u0 = accU[mt][nt][half * 2], u1 = accU[mt][nt][half * 2 + 1];
                    float h0 = __uint_as_float(f2tf(g0 / (1.f + expf(-g0)) * u0));
                    float h1 = __uint_as_float(f2tf(g1 / (1.f + expf(-g1)) * u1));
                    *(float2*)(hrow + wn * 32 + nt * 8 + qc * 2) = make_float2(h0, h1);
                }
            }
        }
}

// ---------------- GEMM2: out[tok] += w * (H Wd), tf32 mma.sync ----------------
__global__ __launch_bounds__(256, 2)
void gemm2_mma(float* __restrict__ out) {
    int e = blockIdx.z;
    int n = g_cnt[e];
    int row0 = blockIdx.y * 128;
    if (row0 >= n) return;
    int col0 = blockIdx.x * 128;

    extern __shared__ char smem[];
    int* toks = (int*)smem;
    float* wts = (float*)(smem + 512);
    uint32_t sb = s2u(smem);
    int tid = threadIdx.x, wid = tid >> 5, l = tid & 31;

    if (tid < 128) {
        int r = row0 + tid;
        toks[tid] = (r < n) ? g_tok[e * CAP + r] : -1;
        wts[tid]  = (r < n) ? g_wt[e * CAP + r] : 0.f;
    }
    __syncthreads();

    int arow = tid >> 1;
    int aseg0 = (tid & 1) * 4;
    int hrow = (row0 + arow < n) ? (row0 + arow) : 0;
    const uint32_t* srcA = (const uint32_t*)g_H + ((size_t)e * CAP + hrow) * F_DIM;
    int brow = tid >> 3, bseg = tid & 7;
    const uint32_t* srcB = g_wdt + (size_t)e * F_DIM * D_DIM + (size_t)brow * D_DIM + col0 + bseg * 4;
    uint32_t adst[4], bdst[4];
#pragma unroll
    for (int j = 0; j < 4; j++) {
        adst[j] = (uint32_t)((arow * SA + (aseg0 + j) * 4) * 4);
        bdst[j] = (uint32_t)((brow * SB + bseg * 4 + j * 32) * 4);
    }

    const int NT = F_DIM / 32;  // 64

#define G2_ISSUE(c) do { \
    uint32_t base_ = sb + BUF0 + ((c) & 1) * STAGE2; \
    int k0_ = (c) * 32; \
    const uint32_t* sa_ = srcA + k0_ + aseg0 * 4; \
    const uint32_t* sb_ = srcB + (size_t)k0_ * D_DIM; \
    CPA16(base_ + adst[0], sa_); \
    CPA16(base_ + adst[1], sa_ + 4); \
    CPA16(base_ + adst[2], sa_ + 8); \
    CPA16(base_ + adst[3], sa_ + 12); \
    CPA16(base_ + ABYTES + bdst[0], sb_); \
    CPA16(base_ + ABYTES + bdst[1], sb_ + 32); \
    CPA16(base_ + ABYTES + bdst[2], sb_ + 64); \
    CPA16(base_ + ABYTES + bdst[3], sb_ + 96); \
} while (0)

    float acc[4][4][4] = {};
    int wm = wid & 1, wn = wid >> 1;
    int qr = l >> 2, qc = l & 3;

    G2_ISSUE(0); CPCOMMIT();
    G2_ISSUE(1); CPCOMMIT();

#pragma unroll 1
    for (int c = 0; c < NT; c++) {
        CPWAIT1();
        __syncthreads();
        const uint32_t* As = (const uint32_t*)(smem + BUF0 + (c & 1) * STAGE2);
        const uint32_t* Bs = As + ABYTES / 4;
#pragma unroll
        for (int ks = 0; ks < 4; ks++) {
            int kk = ks * 8;
            uint32_t af[4][4];
#pragma unroll
            for (int mt = 0; mt < 4; mt++) {
                int r0 = wm * 64 + mt * 16 + qr;
                af[mt][0] = As[r0 * SA + kk + qc];
                af[mt][1] = As[(r0 + 8) * SA + kk + qc];
                af[mt][2] = As[r0 * SA + kk + qc + 4];
                af[mt][3] = As[(r0 + 8) * SA + kk + qc + 4];
            }
            uint32_t bf[4][2];
#pragma unroll
            for (int nt = 0; nt < 4; nt++) {
                int cc = wn * 32 + nt * 8 + qr;
                bf[nt][0] = Bs[(kk + qc) * SB + cc];
                bf[nt][1] = Bs[(kk + qc + 4) * SB + cc];
            }
#pragma unroll
            for (int mt = 0; mt < 4; mt++)
#pragma unroll
                for (int nt = 0; nt < 4; nt++)
                    mma8(acc[mt][nt], af[mt], bf[nt]);
        }
        __syncthreads();
        if (c + 2 < NT) G2_ISSUE(c + 2);
        CPCOMMIT();
    }

    // epilogue: scaled scatter-add
#pragma unroll
    for (int mt = 0; mt < 4; mt++)
#pragma unroll
        for (int half = 0; half < 2; half++) {
            int lrow = wm * 64 + mt * 16 + qr + half * 8;
            int grow = row0 + lrow;
            if (grow < n) {
                int t = toks[lrow];
                float w = wts[lrow];
                float* orow = out + (size_t)t * D_DIM + col0;
#pragma unroll
                for (int nt = 0; nt < 4; nt++) {
                    float v0 = w * acc[mt][nt][half * 2];
                    float v1 = w * acc[mt][nt][half * 2 + 1];
                    atomicAdd(orow + wn * 32 + nt * 8 + qc * 2, v0);
                    atomicAdd(orow + wn * 32 + nt * 8 + qc * 2 + 1, v1);
                }
            }
        }
}

// ---------------- launch ----------------
extern "C" void kernel_launch(void* const* d_in, const int* in_sizes, int n_in,
                              void* d_out, int out_size) {
    const float* x  = (const float*)d_in[0];
    const float* Wr = (const float*)d_in[1];
    const float* Wg = (const float*)d_in[2];
    const float* Wu = (const float*)d_in[3];
    const float* Wd = (const float*)d_in[4];
    float* out = (float*)d_out;

    cudaFuncSetAttribute(gemm1_mma, cudaFuncAttributeMaxDynamicSharedMemorySize, SMEM1);
    cudaFuncSetAttribute(gemm2_mma, cudaFuncAttributeMaxDynamicSharedMemorySize, SMEM2);

    cudaMemsetAsync(out, 0, (size_t)out_size * sizeof(float), 0);
    init_kernel<<<1, 32>>>();
    cvt_all<<<2048, 256>>>(x, Wg, Wu, Wd);
    router_kernel<<<128, 256>>>(x, Wr);
    dim3 g1(F_DIM / 128, CAP / 128, E_EXP);
    gemm1_mma<<<g1, 256, SMEM1>>>(x);
    dim3 g2(D_DIM / 128, CAP / 128, E_EXP);
    gemm2_mma<<<g2, 256, SMEM2>>>(out);
    finalize_kernel<<<1, 32>>>(out, (long long)out_size);
}